// round 3
// baseline (speedup 1.0000x reference)
#include <cuda_runtime.h>
#include <cstdint>

// Problem constants (fixed by the dataset)
#define NN      100000     // nodes
#define IN_DIM  256
#define HID     128
#define OUT_DIM 64

// Scratch: __device__ globals (allocation-free rule)
__device__ float g_support1[(size_t)NN * HID];     // X @ W1            (51.2 MB)
__device__ float g_hidden  [(size_t)NN * HID];     // A @ support1      (51.2 MB)
__device__ float g_support2[(size_t)NN * OUT_DIM]; // relu(hidden)@W2   (25.6 MB)

// ---------------------------------------------------------------------------
// GEMM: out[r0..r0+ROWS, 0..N) = X[r0..r0+ROWS, 0..K) @ W[K, N]
// blockDim = N threads; thread t owns output column t, acc[ROWS] in registers.
// X tile staged in shared (broadcast reads -> conflict-free), W streamed from
// L2 (tiny, fully L2-resident). Optional fused relu on the X load (layer 2).
// ---------------------------------------------------------------------------
template<int ROWS, int K, int N, bool RELU>
__global__ void __launch_bounds__(N) gemm_kernel(
    const float* __restrict__ X, const float* __restrict__ W,
    float* __restrict__ out, int nrows)
{
    __shared__ float Xs[ROWS * K];
    const int t  = threadIdx.x;
    const int r0 = blockIdx.x * ROWS;

    if (r0 + ROWS <= nrows) {
        const float4* Xv = reinterpret_cast<const float4*>(X + (size_t)r0 * K);
        float4* Sv = reinterpret_cast<float4*>(Xs);
        #pragma unroll
        for (int i = t; i < ROWS * K / 4; i += N) {
            float4 v = Xv[i];
            if (RELU) {
                v.x = fmaxf(v.x, 0.f); v.y = fmaxf(v.y, 0.f);
                v.z = fmaxf(v.z, 0.f); v.w = fmaxf(v.w, 0.f);
            }
            Sv[i] = v;
        }
    } else {
        for (int i = t; i < ROWS * K; i += N) {
            int r = i / K;
            float v = (r0 + r < nrows) ? X[(size_t)(r0 + r) * K + (i % K)] : 0.f;
            if (RELU) v = fmaxf(v, 0.f);
            Xs[i] = v;
        }
    }
    __syncthreads();

    float acc[ROWS];
    #pragma unroll
    for (int r = 0; r < ROWS; r++) acc[r] = 0.f;

    #pragma unroll 4
    for (int k = 0; k < K; k++) {
        const float w = __ldg(&W[k * N + t]);
        #pragma unroll
        for (int r = 0; r < ROWS; r++)
            acc[r] += Xs[r * K + k] * w;   // Xs read is a warp broadcast
    }

    #pragma unroll
    for (int r = 0; r < ROWS; r++)
        if (r0 + r < nrows)
            out[(size_t)(r0 + r) * N + t] = acc[r];
}

// ---------------------------------------------------------------------------
// Scatter-aggregate: dst[row[e], :] += src[col[e], :]  for every edge.
// Edge indices are int32 (JAX x64-disabled makes "int64" randint silently
// int32). FEATS/4 lanes per edge group; one lane loads the indices and
// broadcasts via shfl. Each lane: one float4 gather + one red.v4.f32.
// FEATS=128 -> 1 edge/warp; FEATS=64 -> 2 edges/warp.
// ---------------------------------------------------------------------------
template<int FEATS>
__global__ void __launch_bounds__(512) scatter_kernel(
    const int* __restrict__ rows, const int* __restrict__ cols,
    const float* __restrict__ src, float* __restrict__ dst, int n_edges)
{
    constexpr int LPE = FEATS / 4;   // lanes per edge (32 or 16)
    constexpr int EPW = 32 / LPE;    // edges per warp (1 or 2)

    const int warp = (blockIdx.x * blockDim.x + threadIdx.x) >> 5;
    const int lane = threadIdx.x & 31;
    const int e    = warp * EPW + lane / LPE;
    const bool ok  = (e < n_edges);
    const int sub  = lane % LPE;
    const int src_lane = (lane / LPE) * LPE;   // leader lane of this edge group

    int r = 0, c = 0;
    if (ok && sub == 0) { r = rows[e]; c = cols[e]; }
    r = __shfl_sync(0xFFFFFFFFu, r, src_lane);
    c = __shfl_sync(0xFFFFFFFFu, c, src_lane);
    if (!ok) return;

    const float4 v = *reinterpret_cast<const float4*>(src + (size_t)c * FEATS + sub * 4);
    float* p = dst + (size_t)r * FEATS + sub * 4;
    asm volatile("red.global.add.v4.f32 [%0], {%1, %2, %3, %4};"
                 :: "l"(p), "f"(v.x), "f"(v.y), "f"(v.z), "f"(v.w)
                 : "memory");
}

// ---------------------------------------------------------------------------
extern "C" void kernel_launch(void* const* d_in, const int* in_sizes, int n_in,
                              void* d_out, int out_size)
{
    const float* X   = (const float*)d_in[0];
    const int*   ei  = (const int*)d_in[1];     // int32 edge indices
    const float* W1  = (const float*)d_in[2];
    const float* W2  = (const float*)d_in[3];
    float*       out = (float*)d_out;

    const int nrows   = in_sizes[0] / IN_DIM;   // 100000
    const int n_edges = in_sizes[1] / 2;        // 3200000
    const int* e_rows = ei;
    const int* e_cols = ei + n_edges;

    void *p_s1, *p_hid, *p_s2;
    cudaGetSymbolAddress(&p_s1,  g_support1);
    cudaGetSymbolAddress(&p_hid, g_hidden);
    cudaGetSymbolAddress(&p_s2,  g_support2);
    float* support1 = (float*)p_s1;
    float* hidden   = (float*)p_hid;
    float* support2 = (float*)p_s2;

    // Zero the two scatter destinations (graph-capturable async memsets)
    cudaMemsetAsync(hidden, 0, (size_t)nrows * HID * sizeof(float));
    cudaMemsetAsync(out,    0, (size_t)nrows * OUT_DIM * sizeof(float));

    // Layer 1: support1 = X @ W1
    {
        constexpr int ROWS = 32;
        int blocks = (nrows + ROWS - 1) / ROWS;
        gemm_kernel<ROWS, IN_DIM, HID, false><<<blocks, HID>>>(X, W1, support1, nrows);
    }
    // hidden = A @ support1  (atomic scatter): 1 edge per warp
    {
        int warps  = n_edges;
        int blocks = (warps + 15) / 16;        // 512 threads = 16 warps / block
        scatter_kernel<HID><<<blocks, 512>>>(e_rows, e_cols, support1, hidden, n_edges);
    }
    // Layer 2: support2 = relu(hidden) @ W2
    {
        constexpr int ROWS = 32;
        int blocks = (nrows + ROWS - 1) / ROWS;
        gemm_kernel<ROWS, HID, OUT_DIM, true><<<blocks, OUT_DIM>>>(hidden, W2, support2, nrows);
    }
    // out = A @ support2  (atomic scatter): 2 edges per warp
    {
        int warps  = (n_edges + 1) / 2;
        int blocks = (warps + 15) / 16;
        scatter_kernel<OUT_DIM><<<blocks, 512>>>(e_rows, e_cols, support2, out, n_edges);
    }
}

// round 4
// speedup vs baseline: 1.6805x; 1.6805x over previous
#include <cuda_runtime.h>
#include <cstdint>

// Problem constants (fixed by the dataset)
#define NN      100000     // nodes
#define IN_DIM  256
#define HID     128
#define OUT_DIM 64
#define NE_MAX  3200000

typedef unsigned long long u64;

// Scratch: __device__ globals (allocation-free rule)
__device__ float g_support1[(size_t)NN * HID];     // X @ W1            (51.2 MB)
__device__ float g_hidden  [(size_t)NN * HID];     // A @ support1      (51.2 MB)
__device__ float g_support2[(size_t)NN * OUT_DIM]; // relu(hidden)@W2   (25.6 MB)
__device__ int   g_rowstart[NN + 1];               // CSR row offsets
__device__ int   g_cursor  [NN];                   // bucket-fill cursors
__device__ int   g_colsorted[NE_MAX];              // col indices sorted by row

// ---------------------------------------------------------------------------
// f32x2 helpers (Blackwell packed fp32 FMA — 2 FMAs per instruction)
// ---------------------------------------------------------------------------
__device__ __forceinline__ u64 pack2(float lo, float hi) {
    u64 r; asm("mov.b64 %0, {%1, %2};" : "=l"(r) : "f"(lo), "f"(hi)); return r;
}
__device__ __forceinline__ void fma2(u64& d, u64 a, u64 b) {
    asm("fma.rn.f32x2 %0, %1, %2, %0;" : "+l"(d) : "l"(a), "l"(b));
}
__device__ __forceinline__ float2 unpack2(u64 v) {
    float2 f; asm("mov.b64 {%0, %1}, %2;" : "=f"(f.x), "=f"(f.y) : "l"(v)); return f;
}

// ---------------------------------------------------------------------------
// GEMM: out[r0..r0+ROWS, :] = X[r0..r0+ROWS, :] @ W[K, N]   (optional relu on X)
// Thread t owns column t. Row-major X tile in shared; LDS.128 of 4 consecutive
// k-values reinterpreted as 2 x f32x2; k-split accumulator per row; W pair
// packs amortized over all ROWS. Final: acc.lo + acc.hi.
// ---------------------------------------------------------------------------
template<int ROWS, int K, int N, bool RELU>
__global__ void __launch_bounds__(N) gemm2x_kernel(
    const float* __restrict__ X, const float* __restrict__ W,
    float* __restrict__ out, int nrows)
{
    __shared__ float Xs[ROWS * K];
    const int t  = threadIdx.x;
    const int r0 = blockIdx.x * ROWS;

    if (r0 + ROWS <= nrows) {
        const float4* Xv = reinterpret_cast<const float4*>(X + (size_t)r0 * K);
        float4* Sv = reinterpret_cast<float4*>(Xs);
        #pragma unroll
        for (int i = t; i < ROWS * K / 4; i += N) {
            float4 v = Xv[i];
            if (RELU) {
                v.x = fmaxf(v.x, 0.f); v.y = fmaxf(v.y, 0.f);
                v.z = fmaxf(v.z, 0.f); v.w = fmaxf(v.w, 0.f);
            }
            Sv[i] = v;
        }
    } else {
        for (int i = t; i < ROWS * K; i += N) {
            int r = i / K;
            float v = (r0 + r < nrows) ? X[(size_t)(r0 + r) * K + (i % K)] : 0.f;
            if (RELU) v = fmaxf(v, 0.f);
            Xs[i] = v;
        }
    }
    __syncthreads();

    u64 acc[ROWS];
    #pragma unroll
    for (int r = 0; r < ROWS; r++) acc[r] = 0ull;

    const float* Wt = W + t;
    #pragma unroll 1
    for (int k = 0; k < K; k += 4) {
        const float w0 = __ldg(&Wt[(k + 0) * N]);
        const float w1 = __ldg(&Wt[(k + 1) * N]);
        const float w2 = __ldg(&Wt[(k + 2) * N]);
        const float w3 = __ldg(&Wt[(k + 3) * N]);
        const u64 b01 = pack2(w0, w1);
        const u64 b23 = pack2(w2, w3);
        #pragma unroll
        for (int r = 0; r < ROWS; r++) {
            // LDS.128 broadcast (same address across warp): {x0,x1,x2,x3}
            const ulonglong2 xv = *reinterpret_cast<const ulonglong2*>(&Xs[r * K + k]);
            fma2(acc[r], xv.x, b01);
            fma2(acc[r], xv.y, b23);
        }
    }

    #pragma unroll
    for (int r = 0; r < ROWS; r++) {
        const float2 p = unpack2(acc[r]);
        if (r0 + r < nrows)
            out[(size_t)(r0 + r) * N + t] = p.x + p.y;
    }
}

// ---------------------------------------------------------------------------
// CSR build: histogram -> scan -> bucket fill
// ---------------------------------------------------------------------------
__global__ void hist_kernel(const int* __restrict__ rows, int* __restrict__ deg,
                            int n_edges)
{
    int i = blockIdx.x * blockDim.x + threadIdx.x;
    if (i < n_edges) atomicAdd(&deg[rows[i] + 1], 1);   // deg stored at rowstart[r+1]
}

// Single-block inclusive scan over a[1..n] (a[0] stays 0). 1024 threads.
__global__ void scan_kernel(int* __restrict__ a, int n)
{
    __shared__ int sums[1024];
    const int t = threadIdx.x;
    const int chunk = (n + 1023) >> 10;
    const int beg = 1 + t * chunk;
    const int end = min(1 + (t + 1) * chunk, n + 1);

    int s = 0;
    for (int i = beg; i < end; i++) s += a[i];
    sums[t] = s;
    __syncthreads();

    #pragma unroll
    for (int off = 1; off < 1024; off <<= 1) {
        int v = (t >= off) ? sums[t - off] : 0;
        __syncthreads();
        sums[t] += v;
        __syncthreads();
    }

    int prefix = (t == 0) ? 0 : sums[t - 1];
    for (int i = beg; i < end; i++) { prefix += a[i]; a[i] = prefix; }
}

__global__ void fill_kernel(const int* __restrict__ rows, const int* __restrict__ cols,
                            int* __restrict__ cursor, int* __restrict__ colsorted,
                            int n_edges)
{
    int i = blockIdx.x * blockDim.x + threadIdx.x;
    if (i < n_edges) {
        int pos = atomicAdd(&cursor[rows[i]], 1);
        colsorted[pos] = cols[i];
    }
}

// ---------------------------------------------------------------------------
// CSR aggregation: dst[n, :] = sum over edges of bucket n of src[col, :].
// FEATS/4 lanes per node; 1 node/warp (FEATS=128) or 2 nodes/warp (FEATS=64).
// Pure gathers + one streaming float4 write per lane — no atomics.
// ---------------------------------------------------------------------------
template<int FEATS>
__global__ void __launch_bounds__(256) agg_kernel(
    const int* __restrict__ rowstart, const int* __restrict__ colsorted,
    const float* __restrict__ src, float* __restrict__ dst, int n_nodes)
{
    constexpr int LPE = FEATS / 4;   // lanes per node (32 or 16)
    constexpr int NPW = 32 / LPE;    // nodes per warp (1 or 2)

    const int warp = (blockIdx.x * blockDim.x + threadIdx.x) >> 5;
    const int lane = threadIdx.x & 31;
    const int n    = warp * NPW + lane / LPE;
    if (n >= n_nodes) return;
    const int sub  = lane % LPE;

    const int beg = rowstart[n];
    const int end = rowstart[n + 1];

    float4 acc = make_float4(0.f, 0.f, 0.f, 0.f);
    int e = beg;
    for (; e + 4 <= end; e += 4) {
        const int c0 = __ldg(&colsorted[e + 0]);
        const int c1 = __ldg(&colsorted[e + 1]);
        const int c2 = __ldg(&colsorted[e + 2]);
        const int c3 = __ldg(&colsorted[e + 3]);
        const float4 v0 = *reinterpret_cast<const float4*>(src + (size_t)c0 * FEATS + sub * 4);
        const float4 v1 = *reinterpret_cast<const float4*>(src + (size_t)c1 * FEATS + sub * 4);
        const float4 v2 = *reinterpret_cast<const float4*>(src + (size_t)c2 * FEATS + sub * 4);
        const float4 v3 = *reinterpret_cast<const float4*>(src + (size_t)c3 * FEATS + sub * 4);
        acc.x += (v0.x + v1.x) + (v2.x + v3.x);
        acc.y += (v0.y + v1.y) + (v2.y + v3.y);
        acc.z += (v0.z + v1.z) + (v2.z + v3.z);
        acc.w += (v0.w + v1.w) + (v2.w + v3.w);
    }
    for (; e < end; e++) {
        const int c = __ldg(&colsorted[e]);
        const float4 v = *reinterpret_cast<const float4*>(src + (size_t)c * FEATS + sub * 4);
        acc.x += v.x; acc.y += v.y; acc.z += v.z; acc.w += v.w;
    }

    *reinterpret_cast<float4*>(dst + (size_t)n * FEATS + sub * 4) = acc;
}

// ---------------------------------------------------------------------------
extern "C" void kernel_launch(void* const* d_in, const int* in_sizes, int n_in,
                              void* d_out, int out_size)
{
    const float* X   = (const float*)d_in[0];
    const int*   ei  = (const int*)d_in[1];     // int32 edge indices
    const float* W1  = (const float*)d_in[2];
    const float* W2  = (const float*)d_in[3];
    float*       out = (float*)d_out;

    const int nrows   = in_sizes[0] / IN_DIM;   // 100000
    const int n_edges = in_sizes[1] / 2;        // 3200000
    const int* e_rows = ei;
    const int* e_cols = ei + n_edges;

    void *p_s1, *p_hid, *p_s2, *p_rs, *p_cur, *p_cs;
    cudaGetSymbolAddress(&p_s1,  g_support1);
    cudaGetSymbolAddress(&p_hid, g_hidden);
    cudaGetSymbolAddress(&p_s2,  g_support2);
    cudaGetSymbolAddress(&p_rs,  g_rowstart);
    cudaGetSymbolAddress(&p_cur, g_cursor);
    cudaGetSymbolAddress(&p_cs,  g_colsorted);
    float* support1 = (float*)p_s1;
    float* hidden   = (float*)p_hid;
    float* support2 = (float*)p_s2;
    int*   rowstart = (int*)p_rs;
    int*   cursor   = (int*)p_cur;
    int*   colsorted= (int*)p_cs;

    // ---- CSR build (same edge list both layers) ----
    cudaMemsetAsync(rowstart, 0, (NN + 1) * sizeof(int));
    {
        int blocks = (n_edges + 511) / 512;
        hist_kernel<<<blocks, 512>>>(e_rows, rowstart, n_edges);
    }
    scan_kernel<<<1, 1024>>>(rowstart, nrows);
    cudaMemcpyAsync(cursor, rowstart, NN * sizeof(int), cudaMemcpyDeviceToDevice);
    {
        int blocks = (n_edges + 511) / 512;
        fill_kernel<<<blocks, 512>>>(e_rows, e_cols, cursor, colsorted, n_edges);
    }

    // ---- Layer 1: support1 = X @ W1 ----
    {
        constexpr int ROWS = 32;
        int blocks = (nrows + ROWS - 1) / ROWS;
        gemm2x_kernel<ROWS, IN_DIM, HID, false><<<blocks, HID>>>(X, W1, support1, nrows);
    }
    // hidden = A @ support1 (CSR gather-aggregate; 1 node per warp)
    {
        int blocks = (nrows + 7) / 8;            // 8 warps = 8 nodes per block
        agg_kernel<HID><<<blocks, 256>>>(rowstart, colsorted, support1, hidden, nrows);
    }
    // ---- Layer 2: support2 = relu(hidden) @ W2 ----
    {
        constexpr int ROWS = 32;
        int blocks = (nrows + ROWS - 1) / ROWS;
        gemm2x_kernel<ROWS, HID, OUT_DIM, true><<<blocks, OUT_DIM>>>(hidden, W2, support2, nrows);
    }
    // out = A @ support2 (CSR gather-aggregate; 2 nodes per warp)
    {
        int blocks = (nrows + 15) / 16;          // 8 warps = 16 nodes per block
        agg_kernel<OUT_DIM><<<blocks, 256>>>(rowstart, colsorted, support2, out, nrows);
    }
}

// round 5
// speedup vs baseline: 2.0406x; 1.2143x over previous
#include <cuda_runtime.h>
#include <cstdint>

// Problem constants (fixed by the dataset)
#define NN      100000     // nodes
#define IN_DIM  256
#define HID     128
#define OUT_DIM 64
#define NE_MAX  3200000

typedef unsigned long long u64;

// Scratch: __device__ globals (allocation-free rule)
__device__ float g_support1[(size_t)NN * HID];     // X @ W1            (51.2 MB)
__device__ float g_hidden  [(size_t)NN * HID];     // A @ support1      (51.2 MB)
__device__ float g_support2[(size_t)NN * OUT_DIM]; // relu(hidden)@W2   (25.6 MB)
__device__ int   g_rowstart[NN + 1];               // CSR row offsets
__device__ int   g_cursor  [NN];                   // bucket-fill cursors
__device__ int   g_colsorted[NE_MAX];              // col indices sorted by row

// ---------------------------------------------------------------------------
// f32x2 helpers (Blackwell packed fp32 FMA — 2 FMAs per instruction)
// ---------------------------------------------------------------------------
__device__ __forceinline__ u64 pack2(float lo, float hi) {
    u64 r; asm("mov.b64 %0, {%1, %2};" : "=l"(r) : "f"(lo), "f"(hi)); return r;
}
__device__ __forceinline__ void fma2(u64& d, u64 a, u64 b) {
    asm("fma.rn.f32x2 %0, %1, %2, %0;" : "+l"(d) : "l"(a), "l"(b));
}
__device__ __forceinline__ float2 unpack2(u64 v) {
    float2 f; asm("mov.b64 {%0, %1}, %2;" : "=f"(f.x), "=f"(f.y) : "l"(v)); return f;
}

// ---------------------------------------------------------------------------
// Register-tiled GEMM: out[M,N] = X[M,K] @ W[K,N], N == full width (one block
// column). Thread tile = 8 rows x 4 cols; f32x2 lanes = column pairs.
// Per k-step per thread: 8 scalar broadcast LDS (x) + 1 LDS.128 (w)
// feeding 16 FFMA2  ->  ~1 B smem traffic per FMA (4x less than before).
// ---------------------------------------------------------------------------
template<int BM, int N, int BK, int K, bool RELU>
__global__ void __launch_bounds__((BM/8)*(N/4)) gemm_rt_kernel(
    const float* __restrict__ X, const float* __restrict__ W,
    float* __restrict__ out, int nrows)
{
    constexpr int NTC = N / 4;        // thread cols
    constexpr int NTR = BM / 8;       // thread rows
    constexpr int NT  = NTC * NTR;    // 256 threads for both configs
    static_assert(NT == 256, "bad tile");

    __shared__ float Xs[BM][BK];      // row-major, natural
    __shared__ float Ws[BK][N];       // row-major, natural

    const int tid  = threadIdx.x;
    const int tcol = tid % NTC;
    const int trow = tid / NTC;
    const int r0   = blockIdx.x * BM;

    u64 acc[8][2];
    #pragma unroll
    for (int i = 0; i < 8; i++) { acc[i][0] = 0ull; acc[i][1] = 0ull; }

    for (int kc = 0; kc < K; kc += BK) {
        // ---- stage X tile (coalesced float4; zero-pad OOB rows) ----
        constexpr int XF4 = BM * BK / 4;
        #pragma unroll
        for (int i = tid; i < XF4; i += NT) {
            const int m  = i / (BK / 4);
            const int kq = i % (BK / 4);
            float4 v = make_float4(0.f, 0.f, 0.f, 0.f);
            if (r0 + m < nrows) {
                v = *reinterpret_cast<const float4*>(&X[(size_t)(r0 + m) * K + kc + kq * 4]);
                if (RELU) {
                    v.x = fmaxf(v.x, 0.f); v.y = fmaxf(v.y, 0.f);
                    v.z = fmaxf(v.z, 0.f); v.w = fmaxf(v.w, 0.f);
                }
            }
            *reinterpret_cast<float4*>(&Xs[m][kq * 4]) = v;
        }
        // ---- stage W tile (coalesced float4) ----
        constexpr int WF4 = BK * N / 4;
        #pragma unroll
        for (int i = tid; i < WF4; i += NT) {
            const int k  = i / (N / 4);
            const int cq = i % (N / 4);
            *reinterpret_cast<float4*>(&Ws[k][cq * 4]) =
                *reinterpret_cast<const float4*>(&W[(size_t)(kc + k) * N + cq * 4]);
        }
        __syncthreads();

        // ---- compute ----
        #pragma unroll 16
        for (int k = 0; k < BK; k++) {
            const float4 wv = *reinterpret_cast<const float4*>(&Ws[k][tcol * 4]);
            const u64 w01 = pack2(wv.x, wv.y);
            const u64 w23 = pack2(wv.z, wv.w);
            #pragma unroll
            for (int i = 0; i < 8; i++) {
                const float x = Xs[trow * 8 + i][k];   // warp broadcast
                const u64 xx = pack2(x, x);
                fma2(acc[i][0], xx, w01);
                fma2(acc[i][1], xx, w23);
            }
        }
        __syncthreads();
    }

    #pragma unroll
    for (int i = 0; i < 8; i++) {
        const int r = r0 + trow * 8 + i;
        if (r < nrows) {
            const float2 p0 = unpack2(acc[i][0]);
            const float2 p1 = unpack2(acc[i][1]);
            const float4 o = make_float4(p0.x, p0.y, p1.x, p1.y);
            *reinterpret_cast<float4*>(&out[(size_t)r * N + tcol * 4]) = o;
        }
    }
}

// ---------------------------------------------------------------------------
// CSR build: histogram -> scan -> bucket fill
// ---------------------------------------------------------------------------
__global__ void hist_kernel(const int* __restrict__ rows, int* __restrict__ deg,
                            int n_edges)
{
    int i = blockIdx.x * blockDim.x + threadIdx.x;
    if (i < n_edges) atomicAdd(&deg[rows[i] + 1], 1);   // deg stored at rowstart[r+1]
}

// Single-block inclusive scan over a[1..n] (a[0] stays 0). 1024 threads.
__global__ void scan_kernel(int* __restrict__ a, int n)
{
    __shared__ int sums[1024];
    const int t = threadIdx.x;
    const int chunk = (n + 1023) >> 10;
    const int beg = 1 + t * chunk;
    const int end = min(1 + (t + 1) * chunk, n + 1);

    int s = 0;
    for (int i = beg; i < end; i++) s += a[i];
    sums[t] = s;
    __syncthreads();

    #pragma unroll
    for (int off = 1; off < 1024; off <<= 1) {
        int v = (t >= off) ? sums[t - off] : 0;
        __syncthreads();
        sums[t] += v;
        __syncthreads();
    }

    int prefix = (t == 0) ? 0 : sums[t - 1];
    for (int i = beg; i < end; i++) { prefix += a[i]; a[i] = prefix; }
}

__global__ void fill_kernel(const int* __restrict__ rows, const int* __restrict__ cols,
                            int* __restrict__ cursor, int* __restrict__ colsorted,
                            int n_edges)
{
    int i = blockIdx.x * blockDim.x + threadIdx.x;
    if (i < n_edges) {
        int pos = atomicAdd(&cursor[rows[i]], 1);
        colsorted[pos] = cols[i];
    }
}

// ---------------------------------------------------------------------------
// CSR aggregation: dst[n, :] = sum over edges of bucket n of src[col, :].
// FEATS/4 lanes per node; 1 node/warp (FEATS=128) or 2 nodes/warp (FEATS=64).
// Pure gathers + one streaming float4 write per lane — no atomics.
// ---------------------------------------------------------------------------
template<int FEATS>
__global__ void __launch_bounds__(256) agg_kernel(
    const int* __restrict__ rowstart, const int* __restrict__ colsorted,
    const float* __restrict__ src, float* __restrict__ dst, int n_nodes)
{
    constexpr int LPE = FEATS / 4;   // lanes per node (32 or 16)
    constexpr int NPW = 32 / LPE;    // nodes per warp (1 or 2)

    const int warp = (blockIdx.x * blockDim.x + threadIdx.x) >> 5;
    const int lane = threadIdx.x & 31;
    const int n    = warp * NPW + lane / LPE;
    if (n >= n_nodes) return;
    const int sub  = lane % LPE;

    const int beg = rowstart[n];
    const int end = rowstart[n + 1];

    float4 acc = make_float4(0.f, 0.f, 0.f, 0.f);
    int e = beg;
    for (; e + 4 <= end; e += 4) {
        const int c0 = __ldg(&colsorted[e + 0]);
        const int c1 = __ldg(&colsorted[e + 1]);
        const int c2 = __ldg(&colsorted[e + 2]);
        const int c3 = __ldg(&colsorted[e + 3]);
        const float4 v0 = *reinterpret_cast<const float4*>(src + (size_t)c0 * FEATS + sub * 4);
        const float4 v1 = *reinterpret_cast<const float4*>(src + (size_t)c1 * FEATS + sub * 4);
        const float4 v2 = *reinterpret_cast<const float4*>(src + (size_t)c2 * FEATS + sub * 4);
        const float4 v3 = *reinterpret_cast<const float4*>(src + (size_t)c3 * FEATS + sub * 4);
        acc.x += (v0.x + v1.x) + (v2.x + v3.x);
        acc.y += (v0.y + v1.y) + (v2.y + v3.y);
        acc.z += (v0.z + v1.z) + (v2.z + v3.z);
        acc.w += (v0.w + v1.w) + (v2.w + v3.w);
    }
    for (; e < end; e++) {
        const int c = __ldg(&colsorted[e]);
        const float4 v = *reinterpret_cast<const float4*>(src + (size_t)c * FEATS + sub * 4);
        acc.x += v.x; acc.y += v.y; acc.z += v.z; acc.w += v.w;
    }

    *reinterpret_cast<float4*>(dst + (size_t)n * FEATS + sub * 4) = acc;
}

// ---------------------------------------------------------------------------
extern "C" void kernel_launch(void* const* d_in, const int* in_sizes, int n_in,
                              void* d_out, int out_size)
{
    const float* X   = (const float*)d_in[0];
    const int*   ei  = (const int*)d_in[1];     // int32 edge indices
    const float* W1  = (const float*)d_in[2];
    const float* W2  = (const float*)d_in[3];
    float*       out = (float*)d_out;

    const int nrows   = in_sizes[0] / IN_DIM;   // 100000
    const int n_edges = in_sizes[1] / 2;        // 3200000
    const int* e_rows = ei;
    const int* e_cols = ei + n_edges;

    void *p_s1, *p_hid, *p_s2, *p_rs, *p_cur, *p_cs;
    cudaGetSymbolAddress(&p_s1,  g_support1);
    cudaGetSymbolAddress(&p_hid, g_hidden);
    cudaGetSymbolAddress(&p_s2,  g_support2);
    cudaGetSymbolAddress(&p_rs,  g_rowstart);
    cudaGetSymbolAddress(&p_cur, g_cursor);
    cudaGetSymbolAddress(&p_cs,  g_colsorted);
    float* support1 = (float*)p_s1;
    float* hidden   = (float*)p_hid;
    float* support2 = (float*)p_s2;
    int*   rowstart = (int*)p_rs;
    int*   cursor   = (int*)p_cur;
    int*   colsorted= (int*)p_cs;

    // ---- CSR build (same edge list both layers) ----
    cudaMemsetAsync(rowstart, 0, (NN + 1) * sizeof(int));
    {
        int blocks = (n_edges + 511) / 512;
        hist_kernel<<<blocks, 512>>>(e_rows, rowstart, n_edges);
    }
    scan_kernel<<<1, 1024>>>(rowstart, nrows);
    cudaMemcpyAsync(cursor, rowstart, NN * sizeof(int), cudaMemcpyDeviceToDevice);
    {
        int blocks = (n_edges + 511) / 512;
        fill_kernel<<<blocks, 512>>>(e_rows, e_cols, cursor, colsorted, n_edges);
    }

    // ---- Layer 1: support1 = X @ W1  (BM=64, N=128, BK=64, K=256) ----
    {
        constexpr int BM = 64;
        int blocks = (nrows + BM - 1) / BM;
        gemm_rt_kernel<BM, HID, 64, IN_DIM, false><<<blocks, 256>>>(X, W1, support1, nrows);
    }
    // hidden = A @ support1 (CSR gather-aggregate; 1 node per warp)
    {
        int blocks = (nrows + 7) / 8;            // 8 warps = 8 nodes per block
        agg_kernel<HID><<<blocks, 256>>>(rowstart, colsorted, support1, hidden, nrows);
    }
    // ---- Layer 2: support2 = relu(hidden) @ W2  (BM=128, N=64, BK=64, K=128) ----
    {
        constexpr int BM = 128;
        int blocks = (nrows + BM - 1) / BM;
        gemm_rt_kernel<BM, OUT_DIM, 64, HID, true><<<blocks, 256>>>(hidden, W2, support2, nrows);
    }
    // out = A @ support2 (CSR gather-aggregate; 2 nodes per warp)
    {
        int blocks = (nrows + 15) / 16;          // 8 warps = 16 nodes per block
        agg_kernel<OUT_DIM><<<blocks, 256>>>(rowstart, colsorted, support2, out, nrows);
    }
}

// round 6
// speedup vs baseline: 2.1050x; 1.0316x over previous
#include <cuda_runtime.h>
#include <cstdint>

// Problem constants (fixed by the dataset)
#define NN      100000     // nodes
#define IN_DIM  256
#define HID     128
#define OUT_DIM 64
#define NE_MAX  3200000

typedef unsigned long long u64;

// Scratch: __device__ globals (allocation-free rule)
__device__ float g_support1[(size_t)NN * HID];     // X @ W1            (51.2 MB)
__device__ float g_hidden  [(size_t)NN * HID];     // A @ support1      (51.2 MB)
__device__ float g_support2[(size_t)NN * OUT_DIM]; // relu(hidden)@W2   (25.6 MB)
__device__ int   g_rowstart[NN + 1];               // CSR row offsets
__device__ int   g_cursor  [NN];                   // bucket-fill cursors
__device__ int   g_colsorted[NE_MAX];              // col indices sorted by row

// ---------------------------------------------------------------------------
// f32x2 helpers (Blackwell packed fp32 FMA — 2 FMAs per instruction)
// ---------------------------------------------------------------------------
__device__ __forceinline__ u64 pack2(float lo, float hi) {
    u64 r; asm("mov.b64 %0, {%1, %2};" : "=l"(r) : "f"(lo), "f"(hi)); return r;
}
__device__ __forceinline__ void fma2(u64& d, u64 a, u64 b) {
    asm("fma.rn.f32x2 %0, %1, %2, %0;" : "+l"(d) : "l"(a), "l"(b));
}
__device__ __forceinline__ float2 unpack2(u64 v) {
    float2 f; asm("mov.b64 {%0, %1}, %2;" : "=f"(f.x), "=f"(f.y) : "l"(v)); return f;
}

// ---------------------------------------------------------------------------
// Register-tiled GEMM: out[M,N] = X[M,K] @ W[K,N]. Thread tile = 8 rows x 4
// cols (f32x2 lanes = column pairs). Inner loop processes k in PAIRS:
// per 2 k-steps a warp issues 8 LDS.64 x-broadcasts + 2 warp-wide LDS.128
// w-loads = 16 wavefronts against 16 SM-cycles of FFMA2 -> LSU/FMA balanced
// (previous version was 12 wf vs 8 cyc per k = 1.5x LSU-bound).
// ---------------------------------------------------------------------------
template<int BM, int N, int BK, int K, bool RELU>
__global__ void __launch_bounds__((BM/8)*(N/4)) gemm_rt_kernel(
    const float* __restrict__ X, const float* __restrict__ W,
    float* __restrict__ out, int nrows)
{
    constexpr int NTC = N / 4;        // thread cols
    constexpr int NTR = BM / 8;       // thread rows
    constexpr int NT  = NTC * NTR;    // 256 threads for both configs
    static_assert(NT == 256, "bad tile");

    __shared__ float Xs[BM][BK];      // row-major, natural
    __shared__ float Ws[BK][N];       // row-major, natural

    const int tid  = threadIdx.x;
    const int tcol = tid % NTC;
    const int trow = tid / NTC;
    const int r0   = blockIdx.x * BM;

    u64 acc[8][2];
    #pragma unroll
    for (int i = 0; i < 8; i++) { acc[i][0] = 0ull; acc[i][1] = 0ull; }

    for (int kc = 0; kc < K; kc += BK) {
        // ---- stage X tile (coalesced float4; zero-pad OOB rows) ----
        constexpr int XF4 = BM * BK / 4;
        #pragma unroll
        for (int i = tid; i < XF4; i += NT) {
            const int m  = i / (BK / 4);
            const int kq = i % (BK / 4);
            float4 v = make_float4(0.f, 0.f, 0.f, 0.f);
            if (r0 + m < nrows) {
                v = *reinterpret_cast<const float4*>(&X[(size_t)(r0 + m) * K + kc + kq * 4]);
                if (RELU) {
                    v.x = fmaxf(v.x, 0.f); v.y = fmaxf(v.y, 0.f);
                    v.z = fmaxf(v.z, 0.f); v.w = fmaxf(v.w, 0.f);
                }
            }
            *reinterpret_cast<float4*>(&Xs[m][kq * 4]) = v;
        }
        // ---- stage W tile (coalesced float4) ----
        constexpr int WF4 = BK * N / 4;
        #pragma unroll
        for (int i = tid; i < WF4; i += NT) {
            const int k  = i / (N / 4);
            const int cq = i % (N / 4);
            *reinterpret_cast<float4*>(&Ws[k][cq * 4]) =
                *reinterpret_cast<const float4*>(&W[(size_t)(kc + k) * N + cq * 4]);
        }
        __syncthreads();

        // ---- compute: k in pairs ----
        #pragma unroll 8
        for (int k = 0; k < BK; k += 2) {
            const float4 wv0 = *reinterpret_cast<const float4*>(&Ws[k][tcol * 4]);
            const float4 wv1 = *reinterpret_cast<const float4*>(&Ws[k + 1][tcol * 4]);
            const u64 w01a = pack2(wv0.x, wv0.y);
            const u64 w23a = pack2(wv0.z, wv0.w);
            const u64 w01b = pack2(wv1.x, wv1.y);
            const u64 w23b = pack2(wv1.z, wv1.w);
            #pragma unroll
            for (int i = 0; i < 8; i++) {
                const float2 xv = *reinterpret_cast<const float2*>(&Xs[trow * 8 + i][k]);
                const u64 xa = pack2(xv.x, xv.x);
                const u64 xb = pack2(xv.y, xv.y);
                fma2(acc[i][0], xa, w01a);
                fma2(acc[i][1], xa, w23a);
                fma2(acc[i][0], xb, w01b);
                fma2(acc[i][1], xb, w23b);
            }
        }
        __syncthreads();
    }

    #pragma unroll
    for (int i = 0; i < 8; i++) {
        const int r = r0 + trow * 8 + i;
        if (r < nrows) {
            const float2 p0 = unpack2(acc[i][0]);
            const float2 p1 = unpack2(acc[i][1]);
            const float4 o = make_float4(p0.x, p0.y, p1.x, p1.y);
            *reinterpret_cast<float4*>(&out[(size_t)r * N + tcol * 4]) = o;
        }
    }
}

// ---------------------------------------------------------------------------
// CSR build: histogram -> scan -> bucket fill
// ---------------------------------------------------------------------------
__global__ void hist_kernel(const int* __restrict__ rows, int* __restrict__ deg,
                            int n_edges)
{
    int i = blockIdx.x * blockDim.x + threadIdx.x;
    if (i < n_edges) atomicAdd(&deg[rows[i] + 1], 1);   // deg stored at rowstart[r+1]
}

// Single-block inclusive scan over a[1..n] (a[0] stays 0). 1024 threads.
__global__ void scan_kernel(int* __restrict__ a, int n)
{
    __shared__ int sums[1024];
    const int t = threadIdx.x;
    const int chunk = (n + 1023) >> 10;
    const int beg = 1 + t * chunk;
    const int end = min(1 + (t + 1) * chunk, n + 1);

    int s = 0;
    for (int i = beg; i < end; i++) s += a[i];
    sums[t] = s;
    __syncthreads();

    #pragma unroll
    for (int off = 1; off < 1024; off <<= 1) {
        int v = (t >= off) ? sums[t - off] : 0;
        __syncthreads();
        sums[t] += v;
        __syncthreads();
    }

    int prefix = (t == 0) ? 0 : sums[t - 1];
    for (int i = beg; i < end; i++) { prefix += a[i]; a[i] = prefix; }
}

__global__ void fill_kernel(const int* __restrict__ rows, const int* __restrict__ cols,
                            int* __restrict__ cursor, int* __restrict__ colsorted,
                            int n_edges)
{
    int i = blockIdx.x * blockDim.x + threadIdx.x;
    if (i < n_edges) {
        int pos = atomicAdd(&cursor[rows[i]], 1);
        colsorted[pos] = cols[i];
    }
}

// ---------------------------------------------------------------------------
// CSR aggregation: dst[n, :] = sum over edges of bucket n of src[col, :].
// FEATS/4 lanes per node; 8-wide unrolled gather loop for deep MLP against
// the ~250-cycle L2 latency. No atomics.
// ---------------------------------------------------------------------------
template<int FEATS>
__global__ void __launch_bounds__(256) agg_kernel(
    const int* __restrict__ rowstart, const int* __restrict__ colsorted,
    const float* __restrict__ src, float* __restrict__ dst, int n_nodes)
{
    constexpr int LPE = FEATS / 4;   // lanes per node (32 or 16)
    constexpr int NPW = 32 / LPE;    // nodes per warp (1 or 2)

    const int warp = (blockIdx.x * blockDim.x + threadIdx.x) >> 5;
    const int lane = threadIdx.x & 31;
    const int n    = warp * NPW + lane / LPE;
    if (n >= n_nodes) return;
    const int sub  = lane % LPE;

    const int beg = rowstart[n];
    const int end = rowstart[n + 1];

    float4 acc = make_float4(0.f, 0.f, 0.f, 0.f);
    int e = beg;
    for (; e + 8 <= end; e += 8) {
        int cc[8];
        #pragma unroll
        for (int j = 0; j < 8; j++) cc[j] = __ldg(&colsorted[e + j]);
        float4 v[8];
        #pragma unroll
        for (int j = 0; j < 8; j++)
            v[j] = *reinterpret_cast<const float4*>(src + (size_t)cc[j] * FEATS + sub * 4);
        acc.x += ((v[0].x + v[1].x) + (v[2].x + v[3].x)) + ((v[4].x + v[5].x) + (v[6].x + v[7].x));
        acc.y += ((v[0].y + v[1].y) + (v[2].y + v[3].y)) + ((v[4].y + v[5].y) + (v[6].y + v[7].y));
        acc.z += ((v[0].z + v[1].z) + (v[2].z + v[3].z)) + ((v[4].z + v[5].z) + (v[6].z + v[7].z));
        acc.w += ((v[0].w + v[1].w) + (v[2].w + v[3].w)) + ((v[4].w + v[5].w) + (v[6].w + v[7].w));
    }
    for (; e < end; e++) {
        const int c = __ldg(&colsorted[e]);
        const float4 v = *reinterpret_cast<const float4*>(src + (size_t)c * FEATS + sub * 4);
        acc.x += v.x; acc.y += v.y; acc.z += v.z; acc.w += v.w;
    }

    *reinterpret_cast<float4*>(dst + (size_t)n * FEATS + sub * 4) = acc;
}

// ---------------------------------------------------------------------------
extern "C" void kernel_launch(void* const* d_in, const int* in_sizes, int n_in,
                              void* d_out, int out_size)
{
    const float* X   = (const float*)d_in[0];
    const int*   ei  = (const int*)d_in[1];     // int32 edge indices
    const float* W1  = (const float*)d_in[2];
    const float* W2  = (const float*)d_in[3];
    float*       out = (float*)d_out;

    const int nrows   = in_sizes[0] / IN_DIM;   // 100000
    const int n_edges = in_sizes[1] / 2;        // 3200000
    const int* e_rows = ei;
    const int* e_cols = ei + n_edges;

    void *p_s1, *p_hid, *p_s2, *p_rs, *p_cur, *p_cs;
    cudaGetSymbolAddress(&p_s1,  g_support1);
    cudaGetSymbolAddress(&p_hid, g_hidden);
    cudaGetSymbolAddress(&p_s2,  g_support2);
    cudaGetSymbolAddress(&p_rs,  g_rowstart);
    cudaGetSymbolAddress(&p_cur, g_cursor);
    cudaGetSymbolAddress(&p_cs,  g_colsorted);
    float* support1 = (float*)p_s1;
    float* hidden   = (float*)p_hid;
    float* support2 = (float*)p_s2;
    int*   rowstart = (int*)p_rs;
    int*   cursor   = (int*)p_cur;
    int*   colsorted= (int*)p_cs;

    // ---- Fork a side stream: CSR build overlaps with gemm1 ----
    cudaStream_t s2;
    cudaEvent_t evFork, evJoin;
    cudaStreamCreateWithFlags(&s2, cudaStreamNonBlocking);
    cudaEventCreateWithFlags(&evFork, cudaEventDisableTiming);
    cudaEventCreateWithFlags(&evJoin, cudaEventDisableTiming);

    cudaEventRecord(evFork, 0);
    cudaStreamWaitEvent(s2, evFork, 0);

    // CSR build on side stream (independent of gemm1)
    cudaMemsetAsync(rowstart, 0, (NN + 1) * sizeof(int), s2);
    {
        int blocks = (n_edges + 511) / 512;
        hist_kernel<<<blocks, 512, 0, s2>>>(e_rows, rowstart, n_edges);
    }
    scan_kernel<<<1, 1024, 0, s2>>>(rowstart, nrows);
    cudaMemcpyAsync(cursor, rowstart, NN * sizeof(int), cudaMemcpyDeviceToDevice, s2);
    {
        int blocks = (n_edges + 511) / 512;
        fill_kernel<<<blocks, 512, 0, s2>>>(e_rows, e_cols, cursor, colsorted, n_edges);
    }
    cudaEventRecord(evJoin, s2);

    // ---- Layer 1: support1 = X @ W1  (main stream, overlaps CSR) ----
    {
        constexpr int BM = 64;
        int blocks = (nrows + BM - 1) / BM;
        gemm_rt_kernel<BM, HID, 64, IN_DIM, false><<<blocks, 256>>>(X, W1, support1, nrows);
    }

    // join: agg1 needs both gemm1 and the CSR
    cudaStreamWaitEvent(0, evJoin, 0);

    // hidden = A @ support1 (CSR gather-aggregate; 1 node per warp)
    {
        int blocks = (nrows + 7) / 8;
        agg_kernel<HID><<<blocks, 256>>>(rowstart, colsorted, support1, hidden, nrows);
    }
    // ---- Layer 2: support2 = relu(hidden) @ W2 ----
    {
        constexpr int BM = 128;
        int blocks = (nrows + BM - 1) / BM;
        gemm_rt_kernel<BM, OUT_DIM, 64, HID, true><<<blocks, 256>>>(hidden, W2, support2, nrows);
    }
    // out = A @ support2 (CSR gather-aggregate; 2 nodes per warp)
    {
        int blocks = (nrows + 15) / 16;
        agg_kernel<OUT_DIM><<<blocks, 256>>>(rowstart, colsorted, support2, out, nrows);
    }
}

// round 7
// speedup vs baseline: 2.4580x; 1.1677x over previous
#include <cuda_runtime.h>
#include <cstdint>

// Problem constants (fixed by the dataset)
#define NN      100000     // nodes
#define IN_DIM  256
#define HID     128
#define OUT_DIM 64
#define NE_MAX  3200000

typedef unsigned long long u64;
typedef unsigned int u32;

// Scratch: __device__ globals (allocation-free rule)
__device__ float g_support1[(size_t)NN * HID];     // X @ W1            (51.2 MB)
__device__ float g_hidden  [(size_t)NN * HID];     // A @ support1      (51.2 MB)
__device__ float g_support2[(size_t)NN * OUT_DIM]; // relu(hidden)@W2   (25.6 MB)
__device__ int   g_rowstart[NN + 1];               // CSR row offsets
__device__ int   g_cursor  [NN];                   // bucket-fill cursors
__device__ int   g_colsorted[NE_MAX];              // col indices sorted by row

// ---------------------------------------------------------------------------
// f32x2 helpers (Blackwell packed fp32 FMA) — used by the FFMA gemm (layer 2)
// ---------------------------------------------------------------------------
__device__ __forceinline__ u64 pack2(float lo, float hi) {
    u64 r; asm("mov.b64 %0, {%1, %2};" : "=l"(r) : "f"(lo), "f"(hi)); return r;
}
__device__ __forceinline__ void fma2(u64& d, u64 a, u64 b) {
    asm("fma.rn.f32x2 %0, %1, %2, %0;" : "+l"(d) : "l"(a), "l"(b));
}
__device__ __forceinline__ float2 unpack2(u64 v) {
    float2 f; asm("mov.b64 {%0, %1}, %2;" : "=f"(f.x), "=f"(f.y) : "l"(v)); return f;
}

// ---------------------------------------------------------------------------
// tf32 helpers
// ---------------------------------------------------------------------------
__device__ __forceinline__ u32 f32_to_tf32(float f) {
    u32 r; asm("cvt.rna.tf32.f32 %0, %1;" : "=r"(r) : "f"(f)); return r;
}
__device__ __forceinline__ void mma_tf32(
    float& d0, float& d1, float& d2, float& d3,
    u32 a0, u32 a1, u32 a2, u32 a3, u32 b0, u32 b1)
{
    asm("mma.sync.aligned.m16n8k8.row.col.f32.tf32.tf32.f32 "
        "{%0,%1,%2,%3}, {%4,%5,%6,%7}, {%8,%9}, {%0,%1,%2,%3};"
        : "+f"(d0), "+f"(d1), "+f"(d2), "+f"(d3)
        : "r"(a0), "r"(a1), "r"(a2), "r"(a3), "r"(b0), "r"(b1));
}

// ---------------------------------------------------------------------------
// tf32 tensor-core GEMM for layer 1: out[M,128] = X[M,256] @ W[256,128].
// Block 256 threads = 8 warps; BM=128, BN=128, BK=32.
// Warp tile 32x64: warp_m = wid%4, warp_n = wid/4; 2 m-tiles x 8 n-tiles of
// m16n8k8. Padded smem makes all fragment LDS.32 conflict-free:
//   Xs[128][36]: bank(A-frag) = (36*row + k)%32 = 4*quad + tq  -> 32 distinct
//   Ws[32][136]: bank(B-frag) = (136*k + c)%32 = 8*k + c       -> 32 distinct
// Inputs rounded to tf32 (cvt.rna) once during staging.
// ---------------------------------------------------------------------------
__global__ void __launch_bounds__(256, 2) gemm_tf32_kernel(
    const float* __restrict__ X, const float* __restrict__ W,
    float* __restrict__ out, int nrows)
{
    constexpr int BM = 128, BK = 32, BN = 128, KTOT = 256;
    __shared__ u32 Xs[BM][BK + 4];    // pad 4 words
    __shared__ u32 Ws[BK][BN + 8];    // pad 8 words

    const int tid    = threadIdx.x;
    const int wid    = tid >> 5;
    const int lane   = tid & 31;
    const int quad   = lane >> 2;     // 0..7
    const int tq     = lane & 3;      // 0..3
    const int warp_m = wid & 3;       // 0..3 (32 rows each)
    const int warp_n = wid >> 2;      // 0..1 (64 cols each)
    const int r0     = blockIdx.x * BM;

    float d[2][8][4];
    #pragma unroll
    for (int mt = 0; mt < 2; mt++)
        #pragma unroll
        for (int nt = 0; nt < 8; nt++)
            #pragma unroll
            for (int i = 0; i < 4; i++) d[mt][nt][i] = 0.f;

    for (int kc = 0; kc < KTOT; kc += BK) {
        // ---- stage X tile: 128x32 = 1024 float4 loads, 4 per thread ----
        #pragma unroll
        for (int j = 0; j < 4; j++) {
            const int idx = tid + j * 256;
            const int r   = idx >> 3;          // /8
            const int k4  = idx & 7;
            float4 v = make_float4(0.f, 0.f, 0.f, 0.f);
            if (r0 + r < nrows)
                v = *reinterpret_cast<const float4*>(&X[(size_t)(r0 + r) * KTOT + kc + k4 * 4]);
            Xs[r][k4 * 4 + 0] = f32_to_tf32(v.x);
            Xs[r][k4 * 4 + 1] = f32_to_tf32(v.y);
            Xs[r][k4 * 4 + 2] = f32_to_tf32(v.z);
            Xs[r][k4 * 4 + 3] = f32_to_tf32(v.w);
        }
        // ---- stage W tile: 32x128 = 1024 float4 loads, 4 per thread ----
        #pragma unroll
        for (int j = 0; j < 4; j++) {
            const int idx = tid + j * 256;
            const int k   = idx >> 5;          // /32
            const int n4  = idx & 31;
            const float4 v = *reinterpret_cast<const float4*>(&W[(size_t)(kc + k) * BN + n4 * 4]);
            Ws[k][n4 * 4 + 0] = f32_to_tf32(v.x);
            Ws[k][n4 * 4 + 1] = f32_to_tf32(v.y);
            Ws[k][n4 * 4 + 2] = f32_to_tf32(v.z);
            Ws[k][n4 * 4 + 3] = f32_to_tf32(v.w);
        }
        __syncthreads();

        // ---- 4 x k8 steps ----
        #pragma unroll
        for (int k8 = 0; k8 < 4; k8++) {
            const int k0 = k8 * 8;
            u32 a[2][4];
            #pragma unroll
            for (int mt = 0; mt < 2; mt++) {
                const int rb = warp_m * 32 + mt * 16 + quad;
                a[mt][0] = Xs[rb    ][k0 + tq];
                a[mt][1] = Xs[rb + 8][k0 + tq];
                a[mt][2] = Xs[rb    ][k0 + tq + 4];
                a[mt][3] = Xs[rb + 8][k0 + tq + 4];
            }
            u32 b[8][2];
            #pragma unroll
            for (int nt = 0; nt < 8; nt++) {
                const int c = warp_n * 64 + nt * 8 + quad;
                b[nt][0] = Ws[k0 + tq    ][c];
                b[nt][1] = Ws[k0 + tq + 4][c];
            }
            #pragma unroll
            for (int mt = 0; mt < 2; mt++)
                #pragma unroll
                for (int nt = 0; nt < 8; nt++)
                    mma_tf32(d[mt][nt][0], d[mt][nt][1], d[mt][nt][2], d[mt][nt][3],
                             a[mt][0], a[mt][1], a[mt][2], a[mt][3],
                             b[nt][0], b[nt][1]);
        }
        __syncthreads();
    }

    // ---- epilogue: D[row][col]: (c0,c1) at (quad, 2*tq), (c2,c3) at row+8 ----
    #pragma unroll
    for (int mt = 0; mt < 2; mt++) {
        const int rA = r0 + warp_m * 32 + mt * 16 + quad;
        const int rB = rA + 8;
        #pragma unroll
        for (int nt = 0; nt < 8; nt++) {
            const int c = warp_n * 64 + nt * 8 + tq * 2;
            if (rA < nrows)
                *reinterpret_cast<float2*>(&out[(size_t)rA * BN + c]) =
                    make_float2(d[mt][nt][0], d[mt][nt][1]);
            if (rB < nrows)
                *reinterpret_cast<float2*>(&out[(size_t)rB * BN + c]) =
                    make_float2(d[mt][nt][2], d[mt][nt][3]);
        }
    }
}

// ---------------------------------------------------------------------------
// Register-tiled FFMA2 GEMM (layer 2). Thread tile 8x4, k-pair inner loop.
// ---------------------------------------------------------------------------
template<int BM, int N, int BK, int K, bool RELU>
__global__ void __launch_bounds__((BM/8)*(N/4)) gemm_rt_kernel(
    const float* __restrict__ X, const float* __restrict__ W,
    float* __restrict__ out, int nrows)
{
    constexpr int NTC = N / 4;
    constexpr int NTR = BM / 8;
    constexpr int NT  = NTC * NTR;
    static_assert(NT == 256, "bad tile");

    __shared__ float Xs[BM][BK];
    __shared__ float Ws[BK][N];

    const int tid  = threadIdx.x;
    const int tcol = tid % NTC;
    const int trow = tid / NTC;
    const int r0   = blockIdx.x * BM;

    u64 acc[8][2];
    #pragma unroll
    for (int i = 0; i < 8; i++) { acc[i][0] = 0ull; acc[i][1] = 0ull; }

    for (int kc = 0; kc < K; kc += BK) {
        constexpr int XF4 = BM * BK / 4;
        #pragma unroll
        for (int i = tid; i < XF4; i += NT) {
            const int m  = i / (BK / 4);
            const int kq = i % (BK / 4);
            float4 v = make_float4(0.f, 0.f, 0.f, 0.f);
            if (r0 + m < nrows) {
                v = *reinterpret_cast<const float4*>(&X[(size_t)(r0 + m) * K + kc + kq * 4]);
                if (RELU) {
                    v.x = fmaxf(v.x, 0.f); v.y = fmaxf(v.y, 0.f);
                    v.z = fmaxf(v.z, 0.f); v.w = fmaxf(v.w, 0.f);
                }
            }
            *reinterpret_cast<float4*>(&Xs[m][kq * 4]) = v;
        }
        constexpr int WF4 = BK * N / 4;
        #pragma unroll
        for (int i = tid; i < WF4; i += NT) {
            const int k  = i / (N / 4);
            const int cq = i % (N / 4);
            *reinterpret_cast<float4*>(&Ws[k][cq * 4]) =
                *reinterpret_cast<const float4*>(&W[(size_t)(kc + k) * N + cq * 4]);
        }
        __syncthreads();

        #pragma unroll 8
        for (int k = 0; k < BK; k += 2) {
            const float4 wv0 = *reinterpret_cast<const float4*>(&Ws[k][tcol * 4]);
            const float4 wv1 = *reinterpret_cast<const float4*>(&Ws[k + 1][tcol * 4]);
            const u64 w01a = pack2(wv0.x, wv0.y);
            const u64 w23a = pack2(wv0.z, wv0.w);
            const u64 w01b = pack2(wv1.x, wv1.y);
            const u64 w23b = pack2(wv1.z, wv1.w);
            #pragma unroll
            for (int i = 0; i < 8; i++) {
                const float2 xv = *reinterpret_cast<const float2*>(&Xs[trow * 8 + i][k]);
                const u64 xa = pack2(xv.x, xv.x);
                const u64 xb = pack2(xv.y, xv.y);
                fma2(acc[i][0], xa, w01a);
                fma2(acc[i][1], xa, w23a);
                fma2(acc[i][0], xb, w01b);
                fma2(acc[i][1], xb, w23b);
            }
        }
        __syncthreads();
    }

    #pragma unroll
    for (int i = 0; i < 8; i++) {
        const int r = r0 + trow * 8 + i;
        if (r < nrows) {
            const float2 p0 = unpack2(acc[i][0]);
            const float2 p1 = unpack2(acc[i][1]);
            const float4 o = make_float4(p0.x, p0.y, p1.x, p1.y);
            *reinterpret_cast<float4*>(&out[(size_t)r * N + tcol * 4]) = o;
        }
    }
}

// ---------------------------------------------------------------------------
// CSR build: histogram -> scan -> bucket fill
// ---------------------------------------------------------------------------
__global__ void hist_kernel(const int* __restrict__ rows, int* __restrict__ deg,
                            int n_edges)
{
    int i = blockIdx.x * blockDim.x + threadIdx.x;
    if (i < n_edges) atomicAdd(&deg[rows[i] + 1], 1);
}

__global__ void scan_kernel(int* __restrict__ a, int n)
{
    __shared__ int sums[1024];
    const int t = threadIdx.x;
    const int chunk = (n + 1023) >> 10;
    const int beg = 1 + t * chunk;
    const int end = min(1 + (t + 1) * chunk, n + 1);

    int s = 0;
    for (int i = beg; i < end; i++) s += a[i];
    sums[t] = s;
    __syncthreads();

    #pragma unroll
    for (int off = 1; off < 1024; off <<= 1) {
        int v = (t >= off) ? sums[t - off] : 0;
        __syncthreads();
        sums[t] += v;
        __syncthreads();
    }

    int prefix = (t == 0) ? 0 : sums[t - 1];
    for (int i = beg; i < end; i++) { prefix += a[i]; a[i] = prefix; }
}

__global__ void fill_kernel(const int* __restrict__ rows, const int* __restrict__ cols,
                            int* __restrict__ cursor, int* __restrict__ colsorted,
                            int n_edges)
{
    int i = blockIdx.x * blockDim.x + threadIdx.x;
    if (i < n_edges) {
        int pos = atomicAdd(&cursor[rows[i]], 1);
        colsorted[pos] = cols[i];
    }
}

// ---------------------------------------------------------------------------
// CSR aggregation over node range [n0, n0+count).
// ---------------------------------------------------------------------------
template<int FEATS>
__global__ void __launch_bounds__(256) agg_kernel(
    const int* __restrict__ rowstart, const int* __restrict__ colsorted,
    const float* __restrict__ src, float* __restrict__ dst, int n0, int count)
{
    constexpr int LPE = FEATS / 4;
    constexpr int NPW = 32 / LPE;

    const int warp = (blockIdx.x * blockDim.x + threadIdx.x) >> 5;
    const int lane = threadIdx.x & 31;
    const int rel  = warp * NPW + lane / LPE;
    if (rel >= count) return;
    const int n   = n0 + rel;
    const int sub = lane % LPE;

    const int beg = rowstart[n];
    const int end = rowstart[n + 1];

    float4 acc = make_float4(0.f, 0.f, 0.f, 0.f);
    int e = beg;
    for (; e + 8 <= end; e += 8) {
        int cc[8];
        #pragma unroll
        for (int j = 0; j < 8; j++) cc[j] = __ldg(&colsorted[e + j]);
        float4 v[8];
        #pragma unroll
        for (int j = 0; j < 8; j++)
            v[j] = *reinterpret_cast<const float4*>(src + (size_t)cc[j] * FEATS + sub * 4);
        acc.x += ((v[0].x + v[1].x) + (v[2].x + v[3].x)) + ((v[4].x + v[5].x) + (v[6].x + v[7].x));
        acc.y += ((v[0].y + v[1].y) + (v[2].y + v[3].y)) + ((v[4].y + v[5].y) + (v[6].y + v[7].y));
        acc.z += ((v[0].z + v[1].z) + (v[2].z + v[3].z)) + ((v[4].z + v[5].z) + (v[6].z + v[7].z));
        acc.w += ((v[0].w + v[1].w) + (v[2].w + v[3].w)) + ((v[4].w + v[5].w) + (v[6].w + v[7].w));
    }
    for (; e < end; e++) {
        const int c = __ldg(&colsorted[e]);
        const float4 v = *reinterpret_cast<const float4*>(src + (size_t)c * FEATS + sub * 4);
        acc.x += v.x; acc.y += v.y; acc.z += v.z; acc.w += v.w;
    }

    *reinterpret_cast<float4*>(dst + (size_t)n * FEATS + sub * 4) = acc;
}

// ---------------------------------------------------------------------------
extern "C" void kernel_launch(void* const* d_in, const int* in_sizes, int n_in,
                              void* d_out, int out_size)
{
    const float* X   = (const float*)d_in[0];
    const int*   ei  = (const int*)d_in[1];     // int32 edge indices
    const float* W1  = (const float*)d_in[2];
    const float* W2  = (const float*)d_in[3];
    float*       out = (float*)d_out;

    const int nrows   = in_sizes[0] / IN_DIM;   // 100000
    const int n_edges = in_sizes[1] / 2;        // 3200000
    const int* e_rows = ei;
    const int* e_cols = ei + n_edges;

    void *p_s1, *p_hid, *p_s2, *p_rs, *p_cur, *p_cs;
    cudaGetSymbolAddress(&p_s1,  g_support1);
    cudaGetSymbolAddress(&p_hid, g_hidden);
    cudaGetSymbolAddress(&p_s2,  g_support2);
    cudaGetSymbolAddress(&p_rs,  g_rowstart);
    cudaGetSymbolAddress(&p_cur, g_cursor);
    cudaGetSymbolAddress(&p_cs,  g_colsorted);
    float* support1 = (float*)p_s1;
    float* hidden   = (float*)p_hid;
    float* support2 = (float*)p_s2;
    int*   rowstart = (int*)p_rs;
    int*   cursor   = (int*)p_cur;
    int*   colsorted= (int*)p_cs;

    // ---- side stream: CSR build + agg1 tail chunk ----
    cudaStream_t s2;
    cudaEvent_t evFork, evCsr, evG1, evA1b;
    cudaStreamCreateWithFlags(&s2, cudaStreamNonBlocking);
    cudaEventCreateWithFlags(&evFork, cudaEventDisableTiming);
    cudaEventCreateWithFlags(&evCsr,  cudaEventDisableTiming);
    cudaEventCreateWithFlags(&evG1,   cudaEventDisableTiming);
    cudaEventCreateWithFlags(&evA1b,  cudaEventDisableTiming);

    cudaEventRecord(evFork, 0);
    cudaStreamWaitEvent(s2, evFork, 0);

    // CSR build on side stream (overlaps gemm1)
    cudaMemsetAsync(rowstart, 0, (NN + 1) * sizeof(int), s2);
    {
        int blocks = (n_edges + 511) / 512;
        hist_kernel<<<blocks, 512, 0, s2>>>(e_rows, rowstart, n_edges);
    }
    scan_kernel<<<1, 1024, 0, s2>>>(rowstart, nrows);
    cudaMemcpyAsync(cursor, rowstart, NN * sizeof(int), cudaMemcpyDeviceToDevice, s2);
    {
        int blocks = (n_edges + 511) / 512;
        fill_kernel<<<blocks, 512, 0, s2>>>(e_rows, e_cols, cursor, colsorted, n_edges);
    }
    cudaEventRecord(evCsr, s2);

    // ---- Layer 1: support1 = X @ W1 (tf32 tensor cores, main stream) ----
    {
        int blocks = (nrows + 127) / 128;
        gemm_tf32_kernel<<<blocks, 256>>>(X, W1, support1, nrows);
    }
    cudaEventRecord(evG1, 0);

    // Chunk split for agg1/gemm2 pipeline (row-block aligned: 391*128)
    const int C = 50048 < nrows ? 50048 : nrows;

    // s2: agg1 tail chunk [C, nrows) — needs gemm1 + CSR
    cudaStreamWaitEvent(s2, evG1, 0);
    if (nrows > C) {
        int count = nrows - C;
        int blocks = (count + 7) / 8;
        agg_kernel<HID><<<blocks, 256, 0, s2>>>(rowstart, colsorted, support1, hidden, C, count);
    }
    cudaEventRecord(evA1b, s2);

    // main: agg1 head chunk [0, C) — needs CSR
    cudaStreamWaitEvent(0, evCsr, 0);
    {
        int blocks = (C + 7) / 8;
        agg_kernel<HID><<<blocks, 256>>>(rowstart, colsorted, support1, hidden, 0, C);
    }
    // main: gemm2 head chunk (overlaps agg1 tail on s2)
    {
        int blocks = (C + 127) / 128;
        gemm_rt_kernel<128, OUT_DIM, 64, HID, true><<<blocks, 256>>>(hidden, W2, support2, C);
    }
    // join tail agg1, then gemm2 tail chunk
    cudaStreamWaitEvent(0, evA1b, 0);
    if (nrows > C) {
        int count = nrows - C;
        int blocks = (count + 127) / 128;
        gemm_rt_kernel<128, OUT_DIM, 64, HID, true><<<blocks, 256>>>(
            hidden + (size_t)C * HID, W2, support2 + (size_t)C * OUT_DIM, count);
    }
    // out = A @ support2 (needs all of support2)
    {
        int blocks = (nrows + 15) / 16;
        agg_kernel<OUT_DIM><<<blocks, 256>>>(rowstart, colsorted, support2, out, 0, nrows);
    }
}